// round 2
// baseline (speedup 1.0000x reference)
#include <cuda_runtime.h>
#include <cuda_bf16.h>

// Problem constants (fixed by the dataset)
#define NN 50000      // nodes
#define NE 800000     // edges
#define DM 64         // d_model
#define DE 32         // d_edge
#define DH 256        // d_hidden
#define NG 64         // graphs
#define EPS 1e-5f

// ---------------- scratch (no allocs allowed) ----------------
__device__ float g_P[(size_t)NN * 512];      // per-node projections: [0:256)=h@W1_dst, [256:512)=h@W1_src
__device__ float g_agg[(size_t)NN * DM];     // aggregated messages

// ---------------- f32x2 helpers (ptxas never auto-emits these) ----------------
__device__ __forceinline__ void ffma2(unsigned long long &acc, unsigned long long a, unsigned long long b) {
    asm("fma.rn.f32x2 %0, %1, %2, %0;" : "+l"(acc) : "l"(a), "l"(b));
}
__device__ __forceinline__ void fadd2(unsigned long long &acc, unsigned long long a) {
    asm("add.rn.f32x2 %0, %0, %1;" : "+l"(acc) : "l"(a));
}
__device__ __forceinline__ unsigned long long pack2(float lo, float hi) {
    unsigned long long r;
    asm("mov.b64 %0, {%1, %2};" : "=l"(r) : "f"(lo), "f"(hi));
    return r;
}
__device__ __forceinline__ float2 unpack2(unsigned long long v) {
    float2 f;
    asm("mov.b64 {%0, %1}, %2;" : "=f"(f.x), "=f"(f.y) : "l"(v));
    return f;
}
__device__ __forceinline__ float silu(float t) {
    return t / (1.0f + __expf(-t));
}

// ---------------- kernel 0: zero the aggregation buffer ----------------
__global__ void zero_agg_kernel() {
    int i = blockIdx.x * blockDim.x + threadIdx.x;
    if (i < NN * DM) g_agg[i] = 0.0f;
}

// ---------------- kernel 1: P[n] = h[n] @ [W1_dst ; W1_src] ----------------
// block = 256 threads, 16 nodes per block; thread owns one column pair of 512.
__global__ __launch_bounds__(256) void precompute_P(
    const float* __restrict__ h, const float* __restrict__ w1)
{
    const int NT = 16;
    __shared__ __align__(16) unsigned long long hs2[NT][DM];  // duplicated h values, 8KB
    int tid = threadIdx.x;
    int n0 = blockIdx.x * NT;

    for (int idx = tid; idx < NT * DM; idx += 256) {
        float v = h[(size_t)(n0 + idx / DM) * DM + (idx % DM)];
        hs2[idx / DM][idx % DM] = pack2(v, v);
    }
    __syncthreads();

    int cp = tid;  // 0..255; jj = 2*cp covers 512 output cols
    // cp<128 -> W1 rows 0..63 (dst part), cols 2cp ; cp>=128 -> rows 64..127 (src part), cols 2(cp-128)
    const float* wbase = (cp < 128) ? (w1 + 2 * cp) : (w1 + 64 * DH + 2 * (cp - 128));

    unsigned long long acc[NT];
#pragma unroll
    for (int i = 0; i < NT; i++) acc[i] = 0ull;

    for (int k = 0; k < DM; k++) {
        unsigned long long w = *(const unsigned long long*)(wbase + (size_t)k * DH);
#pragma unroll
        for (int i = 0; i < NT; i++) ffma2(acc[i], hs2[i][k], w);
    }
#pragma unroll
    for (int i = 0; i < NT; i++) {
        *(unsigned long long*)(g_P + (size_t)(n0 + i) * 512 + 2 * cp) = acc[i];
    }
}

// ---------------- kernel 2: edge MLP + scatter-add ----------------
// t = silu(P_dst[dst] + P_src[src] + e@W1_e + b1) ; m = t@W2 + b2 ; agg[dst] += m
// block = 256 threads, 16 edges per block.
__global__ __launch_bounds__(256) void edge_kernel(
    const float* __restrict__ ea, const int* __restrict__ eidx,
    const float* __restrict__ w1, const float* __restrict__ b1,
    const float* __restrict__ w2, const float* __restrict__ b2)
{
    const int ET = 16;
    __shared__ __align__(16) unsigned long long es2[ET][DE];  // duplicated edge attr, 4KB
    __shared__ __align__(16) float T[ET][DH];                 // hidden activations, 16KB
    __shared__ int dsts[ET];
    __shared__ int srcs[ET];

    int tid = threadIdx.x;
    long long e0 = (long long)blockIdx.x * ET;

    for (int idx = tid; idx < ET * DE; idx += 256) {
        float v = ea[e0 * DE + idx];
        es2[idx / DE][idx % DE] = pack2(v, v);
    }
    if (tid < ET)                dsts[tid]      = eidx[NE + e0 + tid];      // edge_index[1] = dst
    if (tid >= ET && tid < 2*ET) srcs[tid - ET] = eidx[e0 + tid - ET];      // edge_index[0] = src
    __syncthreads();

    // ---- Stage A: hidden layer ----
    {
        int cp = tid & 127;   // column pair (cols 2cp, 2cp+1)
        int hg = tid >> 7;    // 0/1 -> edges [8*hg, 8*hg+8)
        unsigned long long wreg[DE];
#pragma unroll
        for (int k = 0; k < DE; k++)
            wreg[k] = *(const unsigned long long*)(w1 + (size_t)(128 + k) * DH + 2 * cp);
        unsigned long long bpair = *(const unsigned long long*)(b1 + 2 * cp);

#pragma unroll 2
        for (int ii = 0; ii < 8; ii++) {
            int i = hg * 8 + ii;
            int d = dsts[i], s = srcs[i];
            unsigned long long pd = *(const unsigned long long*)(g_P + (size_t)d * 512 + 2 * cp);
            unsigned long long ps = *(const unsigned long long*)(g_P + (size_t)s * 512 + 256 + 2 * cp);
            unsigned long long a0 = bpair, a1 = 0ull;  // split dep chain
#pragma unroll
            for (int k = 0; k < DE; k += 2) {
                ffma2(a0, es2[i][k],     wreg[k]);
                ffma2(a1, es2[i][k + 1], wreg[k + 1]);
            }
            fadd2(a0, a1); fadd2(a0, pd); fadd2(a0, ps);
            float2 t = unpack2(a0);
            T[i][2 * cp]     = silu(t.x);
            T[i][2 * cp + 1] = silu(t.y);
        }
    }
    __syncthreads();

    // ---- Stage B: output layer + atomic scatter ----
    {
        int c = tid & 63;     // output channel
        int g = tid >> 6;     // 0..3 -> edges g, g+4, g+8, g+12
        unsigned long long acc[4] = {0ull, 0ull, 0ull, 0ull};
#pragma unroll 8
        for (int j = 0; j < DH; j += 2) {
            unsigned long long wp = pack2(w2[(size_t)j * DM + c], w2[(size_t)(j + 1) * DM + c]);
#pragma unroll
            for (int q = 0; q < 4; q++) {
                unsigned long long tp = *(const unsigned long long*)&T[g + 4 * q][j];
                ffma2(acc[q], tp, wp);
            }
        }
        float bb = b2[c];
#pragma unroll
        for (int q = 0; q < 4; q++) {
            int i = g + 4 * q;
            float2 a = unpack2(acc[q]);
            atomicAdd(g_agg + (size_t)dsts[i] * DM + c, a.x + a.y + bb);
        }
    }
}

// ---------------- kernel 3: node update MLP + residual ----------------
// out[n] = h[n] + ( silu([h,agg] @ uw1 + ub1) @ uw2 + ub2 )
__global__ __launch_bounds__(256) void node_kernel(
    const float* __restrict__ h,
    const float* __restrict__ uw1, const float* __restrict__ ub1,
    const float* __restrict__ uw2, const float* __restrict__ ub2,
    float* __restrict__ out)
{
    const int NT = 16;
    __shared__ __align__(16) unsigned long long ins2[NT][2 * DM];  // duplicated [h|agg], 16KB
    __shared__ __align__(16) float T[NT][DH];                      // 16KB
    int tid = threadIdx.x;
    int n0 = blockIdx.x * NT;

    for (int idx = tid; idx < NT * 2 * DM; idx += 256) {
        int i = idx / (2 * DM), k = idx % (2 * DM);
        float v = (k < DM) ? h[(size_t)(n0 + i) * DM + k]
                           : g_agg[(size_t)(n0 + i) * DM + (k - DM)];
        ins2[i][k] = pack2(v, v);
    }
    __syncthreads();

    // ---- Stage A ----
    {
        int cp = tid & 127;
        int hg = tid >> 7;
        unsigned long long bpair = *(const unsigned long long*)(ub1 + 2 * cp);
        unsigned long long acc[8];
#pragma unroll
        for (int ii = 0; ii < 8; ii++) acc[ii] = bpair;
        for (int k = 0; k < 2 * DM; k++) {
            unsigned long long w = *(const unsigned long long*)(uw1 + (size_t)k * DH + 2 * cp);
#pragma unroll
            for (int ii = 0; ii < 8; ii++) ffma2(acc[ii], ins2[hg * 8 + ii][k], w);
        }
#pragma unroll
        for (int ii = 0; ii < 8; ii++) {
            int i = hg * 8 + ii;
            float2 t = unpack2(acc[ii]);
            T[i][2 * cp]     = silu(t.x);
            T[i][2 * cp + 1] = silu(t.y);
        }
    }
    __syncthreads();

    // ---- Stage B + residual ----
    {
        int c = tid & 63;
        int g = tid >> 6;
        unsigned long long acc[4] = {0ull, 0ull, 0ull, 0ull};
#pragma unroll 8
        for (int j = 0; j < DH; j += 2) {
            unsigned long long wp = pack2(uw2[(size_t)j * DM + c], uw2[(size_t)(j + 1) * DM + c]);
#pragma unroll
            for (int q = 0; q < 4; q++) {
                unsigned long long tp = *(const unsigned long long*)&T[g + 4 * q][j];
                ffma2(acc[q], tp, wp);
            }
        }
        float bb = ub2[c];
#pragma unroll
        for (int q = 0; q < 4; q++) {
            int i = g + 4 * q;
            size_t o = (size_t)(n0 + i) * DM + c;
            float2 a = unpack2(acc[q]);
            out[o] = h[o] + a.x + a.y + bb;
        }
    }
}

// ---------------- kernel 4: GraphNorm (in place on out) ----------------
__device__ __forceinline__ int lbound32(const int* a, int n, int key) {
    int lo = 0, hi = n;
    while (lo < hi) { int mid = (lo + hi) >> 1; if (a[mid] < key) lo = mid + 1; else hi = mid; }
    return lo;
}

__global__ __launch_bounds__(256) void graphnorm_kernel(
    const int* __restrict__ batch,
    const float* __restrict__ weight, const float* __restrict__ bias,
    const float* __restrict__ alpha, float* __restrict__ out)
{
    int gph = blockIdx.x;
    __shared__ int s_lo, s_hi;
    __shared__ float red[4][DM];
    if (threadIdx.x == 0) s_lo = lbound32(batch, NN, gph);
    if (threadIdx.x == 1) s_hi = lbound32(batch, NN, gph + 1);
    __syncthreads();
    int lo = s_lo, hi = s_hi;
    float fcnt = (float)max(hi - lo, 1);

    int c = threadIdx.x & 63;
    int r = threadIdx.x >> 6;

    float sum = 0.0f;
    for (int n = lo + r; n < hi; n += 4) sum += out[(size_t)n * DM + c];
    red[r][c] = sum;
    __syncthreads();
    float mean = (red[0][c] + red[1][c] + red[2][c] + red[3][c]) / fcnt;
    float am = alpha[c] * mean;
    __syncthreads();

    float sq = 0.0f;
    for (int n = lo + r; n < hi; n += 4) {
        float d = out[(size_t)n * DM + c] - am;
        sq += d * d;
    }
    red[r][c] = sq;
    __syncthreads();
    float var = (red[0][c] + red[1][c] + red[2][c] + red[3][c]) / fcnt;
    float istd = rsqrtf(var + EPS);
    float w = weight[c], b = bias[c];

    for (int n = lo + r; n < hi; n += 4) {
        size_t o = (size_t)n * DM + c;
        out[o] = w * (out[o] - am) * istd + b;
    }
}

// ---------------- launch ----------------
extern "C" void kernel_launch(void* const* d_in, const int* in_sizes, int n_in,
                              void* d_out, int out_size)
{
    (void)in_sizes; (void)n_in; (void)out_size;
    const float* h       = (const float*)d_in[0];
    const float* ea      = (const float*)d_in[1];
    const int*   eidx    = (const int*)d_in[2];    // JAX x64 disabled -> int32
    const int*   batch   = (const int*)d_in[3];    // JAX x64 disabled -> int32
    const float* msg_w1  = (const float*)d_in[4];
    const float* msg_b1  = (const float*)d_in[5];
    const float* msg_w2  = (const float*)d_in[6];
    const float* msg_b2  = (const float*)d_in[7];
    const float* upd_w1  = (const float*)d_in[8];
    const float* upd_b1  = (const float*)d_in[9];
    const float* upd_w2  = (const float*)d_in[10];
    const float* upd_b2  = (const float*)d_in[11];
    const float* gn_w    = (const float*)d_in[12];
    const float* gn_b    = (const float*)d_in[13];
    const float* gn_a    = (const float*)d_in[14];
    float* out = (float*)d_out;

    zero_agg_kernel<<<(NN * DM + 255) / 256, 256>>>();
    precompute_P<<<NN / 16, 256>>>(h, msg_w1);
    edge_kernel<<<NE / 16, 256>>>(ea, eidx, msg_w1, msg_b1, msg_w2, msg_b2);
    node_kernel<<<NN / 16, 256>>>(h, upd_w1, upd_b1, upd_w2, upd_b2, out);
    graphnorm_kernel<<<NG, 256>>>(batch, gn_w, gn_b, gn_a, out);
}

// round 4
// speedup vs baseline: 1.2440x; 1.2440x over previous
#include <cuda_runtime.h>
#include <cstdint>

// Problem constants
#define NN 50000
#define NE 800000
#define DM 64
#define DE 32
#define DH 256
#define NG 64
#define EPS 1e-5f

// ---------------- scratch ----------------
__device__ float    g_agg[(size_t)NN * DM];
__device__ unsigned g_w1t[256 * 160];   // W1^T tf32 bits: [n][k]   (k = 160 input dims)
__device__ unsigned g_w2t[64 * 256];    // W2^T tf32 bits: [c][j]

// ---------------- helpers ----------------
__device__ __forceinline__ unsigned tf32u(float x) {
    unsigned u;
    asm("cvt.rna.tf32.f32 %0, %1;" : "=r"(u) : "f"(x));
    return u;
}
__device__ __forceinline__ float silu(float t) { return t / (1.0f + __expf(-t)); }

// mma.sync m16n8k8 tf32 (baseline PTX, works on plain sm_103 target -> fallback HMMA)
__device__ __forceinline__ void mma_tf32(float& d0, float& d1, float& d2, float& d3,
                                         unsigned a0, unsigned a1, unsigned a2, unsigned a3,
                                         unsigned b0, unsigned b1) {
    asm volatile(
        "mma.sync.aligned.m16n8k8.row.col.f32.tf32.tf32.f32 "
        "{%0,%1,%2,%3}, {%4,%5,%6,%7}, {%8,%9}, {%0,%1,%2,%3};"
        : "+f"(d0), "+f"(d1), "+f"(d2), "+f"(d3)
        : "r"(a0), "r"(a1), "r"(a2), "r"(a3), "r"(b0), "r"(b1));
}

// f32x2 helpers for the FFMA node kernel
__device__ __forceinline__ void ffma2(unsigned long long &acc, unsigned long long a, unsigned long long b) {
    asm("fma.rn.f32x2 %0, %1, %2, %0;" : "+l"(acc) : "l"(a), "l"(b));
}
__device__ __forceinline__ unsigned long long pack2(float lo, float hi) {
    unsigned long long r;
    asm("mov.b64 %0, {%1, %2};" : "=l"(r) : "f"(lo), "f"(hi));
    return r;
}
__device__ __forceinline__ float2 unpack2(unsigned long long v) {
    float2 f;
    asm("mov.b64 {%0, %1}, %2;" : "=f"(f.x), "=f"(f.y) : "l"(v));
    return f;
}

// ---------------- kernel 0: zero agg ----------------
__global__ void zero_agg_kernel() {
    int i = blockIdx.x * blockDim.x + threadIdx.x;
    if (i < NN * DM) g_agg[i] = 0.0f;
}

// ---------------- weight transposes + tf32 rounding (tiny) ----------------
__global__ void transpose_w1(const float* __restrict__ w1) {
    int k = blockIdx.x;        // 0..159
    int n = threadIdx.x;       // 0..255
    g_w1t[(size_t)n * 160 + k] = tf32u(w1[(size_t)k * 256 + n]);
}
__global__ void transpose_w2(const float* __restrict__ w2) {
    int c = blockIdx.x;        // 0..63
    int j = threadIdx.x;       // 0..255
    g_w2t[(size_t)c * 256 + j] = tf32u(w2[(size_t)j * 64 + c]);
}

// ---------------- edge MLP via mma.sync tf32 ----------------
// Block: 128 edges, 256 threads (8 warps; warp w -> rows 16w..16w+15).
// Shared layout (bytes), strides padded for conflict-free fragment LDS:
//   sA  [128][164] tf32   A = [h_dst | h_src | ea]
//   sW1 [64][164]  tf32   W1^T chunk (64 output cols x 160 k)
//   sT  [128][68]  tf32   silu hidden chunk
//   sW2 [64][68]   tf32   W2^T chunk (64 out x 64 k-chunk)
#define SM_DST 0
#define SM_SRC 512
#define SM_B1  1024
#define SM_B2  2048
#define SM_A   2560
#define SM_W1  86528
#define SM_T   128512
#define SM_W2  163328
#define SM_TOT 180736

__global__ __launch_bounds__(256, 1) void edge_mma_kernel(
    const float* __restrict__ h, const float* __restrict__ ea,
    const int* __restrict__ eidx,
    const float* __restrict__ b1, const float* __restrict__ b2)
{
    extern __shared__ char smem[];
    int*      s_dst = (int*)(smem + SM_DST);
    int*      s_src = (int*)(smem + SM_SRC);
    float*    s_b1  = (float*)(smem + SM_B1);
    float*    s_b2  = (float*)(smem + SM_B2);
    unsigned* sA    = (unsigned*)(smem + SM_A);
    unsigned* sW1   = (unsigned*)(smem + SM_W1);
    unsigned* sT    = (unsigned*)(smem + SM_T);
    unsigned* sW2   = (unsigned*)(smem + SM_W2);

    const int tid = threadIdx.x;
    const int w   = tid >> 5;
    const int lane = tid & 31;
    const int r4 = lane >> 2;       // 0..7
    const int c4 = lane & 3;        // 0..3
    const int e0 = blockIdx.x * 128;

    if (tid < 128) s_dst[tid] = eidx[NE + e0 + tid];          // edge_index[1] = dst
    else           s_src[tid - 128] = eidx[e0 + tid - 128];   // edge_index[0] = src
    s_b1[tid] = b1[tid];
    if (tid < 64) s_b2[tid] = b2[tid];
    __syncthreads();

    // ---- gather A tile [128 x 160] tf32 ----
    for (int idx = tid; idx < 128 * 40; idx += 256) {
        int r = idx / 40, cc = (idx % 40) * 4;
        const float4* src;
        if (cc < 64)       src = (const float4*)(h + (size_t)s_dst[r] * 64 + cc);
        else if (cc < 128) src = (const float4*)(h + (size_t)s_src[r] * 64 + (cc - 64));
        else               src = (const float4*)(ea + (size_t)(e0 + r) * 32 + (cc - 128));
        float4 v = *src;
        uint4 u;
        u.x = tf32u(v.x); u.y = tf32u(v.y); u.z = tf32u(v.z); u.w = tf32u(v.w);
        *(uint4*)(sA + r * 164 + cc) = u;
    }

    const int R0 = 16 * w;
    float acc2[8][4];
#pragma unroll
    for (int t = 0; t < 8; t++)
#pragma unroll
        for (int j = 0; j < 4; j++) acc2[t][j] = 0.0f;

    const unsigned* pa  = sA + (R0 + r4) * 164 + c4;   // GEMM1 A base (rows +0 / +8 via +8*164)
    const unsigned* pt  = sT + (R0 + r4) * 68 + c4;    // GEMM2 A base

    for (int q = 0; q < 4; q++) {
        __syncthreads();   // previous chunk's readers done before overwrite
        // load W1^T chunk [64 x 160]
        for (int idx = tid; idx < 64 * 40; idx += 256) {
            int nl = idx / 40, cc = (idx % 40) * 4;
            *(uint4*)(sW1 + nl * 164 + cc) =
                *(const uint4*)(g_w1t + (size_t)(q * 64 + nl) * 160 + cc);
        }
        // load W2^T chunk [64 x 64] (k = cols 64q..64q+63)
        for (int idx = tid; idx < 64 * 16; idx += 256) {
            int c = idx / 16, j4 = (idx % 16) * 4;
            *(uint4*)(sW2 + c * 68 + j4) =
                *(const uint4*)(g_w2t + (size_t)c * 256 + q * 64 + j4);
        }
        __syncthreads();

        // ---- GEMM1: D1chunk[16x64 per warp] = A[16x160] @ W1t_chunk ----
        float acc1[8][4];
#pragma unroll
        for (int t = 0; t < 8; t++)
#pragma unroll
            for (int j = 0; j < 4; j++) acc1[t][j] = 0.0f;

        for (int ks = 0; ks < 20; ks++) {
            int k0 = ks * 8;
            unsigned a0 = pa[k0],            a2 = pa[k0 + 4];
            unsigned a1 = pa[8 * 164 + k0],  a3 = pa[8 * 164 + k0 + 4];
#pragma unroll
            for (int t = 0; t < 8; t++) {
                const unsigned* pb = sW1 + (8 * t + r4) * 164 + c4;
                mma_tf32(acc1[t][0], acc1[t][1], acc1[t][2], acc1[t][3],
                         a0, a1, a2, a3, pb[k0], pb[k0 + 4]);
            }
        }

        // ---- +b1, silu, tf32 -> sT (own rows only) ----
#pragma unroll
        for (int t = 0; t < 8; t++) {
            int col = 8 * t + 2 * c4;
            int gc  = 64 * q + col;
            float bb0 = s_b1[gc], bb1 = s_b1[gc + 1];
            uint2 lo, hi;
            lo.x = tf32u(silu(acc1[t][0] + bb0));
            lo.y = tf32u(silu(acc1[t][1] + bb1));
            hi.x = tf32u(silu(acc1[t][2] + bb0));
            hi.y = tf32u(silu(acc1[t][3] + bb1));
            *(uint2*)(sT + (R0 + r4) * 68 + col)       = lo;
            *(uint2*)(sT + (R0 + 8 + r4) * 68 + col)   = hi;
        }
        __syncwarp();

        // ---- GEMM2 partial: acc2 += Tchunk[16x64] @ W2t_chunk ----
        for (int kc = 0; kc < 8; kc++) {
            int k0 = kc * 8;
            unsigned a0 = pt[k0],           a2 = pt[k0 + 4];
            unsigned a1 = pt[8 * 68 + k0],  a3 = pt[8 * 68 + k0 + 4];
#pragma unroll
            for (int t = 0; t < 8; t++) {
                const unsigned* pb = sW2 + (8 * t + r4) * 68 + c4;
                mma_tf32(acc2[t][0], acc2[t][1], acc2[t][2], acc2[t][3],
                         a0, a1, a2, a3, pb[k0], pb[k0 + 4]);
            }
        }
        __syncwarp();
    }

    // ---- epilogue: +b2, vectorized reduction scatter into g_agg ----
    {
        int row0 = R0 + r4, row1 = R0 + 8 + r4;
        int d0i = s_dst[row0], d1i = s_dst[row1];
#pragma unroll
        for (int t = 0; t < 8; t++) {
            int col = 8 * t + 2 * c4;
            float bb0 = s_b2[col], bb1 = s_b2[col + 1];
            float x0 = acc2[t][0] + bb0, x1 = acc2[t][1] + bb1;
            float x2 = acc2[t][2] + bb0, x3 = acc2[t][3] + bb1;
            asm volatile("red.global.add.v2.f32 [%0], {%1,%2};"
                         :: "l"(g_agg + (size_t)d0i * 64 + col), "f"(x0), "f"(x1) : "memory");
            asm volatile("red.global.add.v2.f32 [%0], {%1,%2};"
                         :: "l"(g_agg + (size_t)d1i * 64 + col), "f"(x2), "f"(x3) : "memory");
        }
    }
}

// ---------------- node update MLP + residual (FFMA f32x2, known-good) ----------------
__global__ __launch_bounds__(256) void node_kernel(
    const float* __restrict__ h,
    const float* __restrict__ uw1, const float* __restrict__ ub1,
    const float* __restrict__ uw2, const float* __restrict__ ub2,
    float* __restrict__ out)
{
    const int NT = 16;
    __shared__ __align__(16) unsigned long long ins2[NT][2 * DM];
    __shared__ __align__(16) float T[NT][DH];
    int tid = threadIdx.x;
    int n0 = blockIdx.x * NT;

    for (int idx = tid; idx < NT * 2 * DM; idx += 256) {
        int i = idx / (2 * DM), k = idx % (2 * DM);
        float v = (k < DM) ? h[(size_t)(n0 + i) * DM + k]
                           : g_agg[(size_t)(n0 + i) * DM + (k - DM)];
        ins2[i][k] = pack2(v, v);
    }
    __syncthreads();

    {
        int cp = tid & 127;
        int hg = tid >> 7;
        unsigned long long bpair = *(const unsigned long long*)(ub1 + 2 * cp);
        unsigned long long acc[8];
#pragma unroll
        for (int ii = 0; ii < 8; ii++) acc[ii] = bpair;
        for (int k = 0; k < 2 * DM; k++) {
            unsigned long long wv = *(const unsigned long long*)(uw1 + (size_t)k * DH + 2 * cp);
#pragma unroll
            for (int ii = 0; ii < 8; ii++) ffma2(acc[ii], ins2[hg * 8 + ii][k], wv);
        }
#pragma unroll
        for (int ii = 0; ii < 8; ii++) {
            int i = hg * 8 + ii;
            float2 t = unpack2(acc[ii]);
            T[i][2 * cp]     = silu(t.x);
            T[i][2 * cp + 1] = silu(t.y);
        }
    }
    __syncthreads();

    {
        int c = tid & 63;
        int g = tid >> 6;
        unsigned long long acc[4] = {0ull, 0ull, 0ull, 0ull};
#pragma unroll 8
        for (int j = 0; j < DH; j += 2) {
            unsigned long long wp = pack2(uw2[(size_t)j * DM + c], uw2[(size_t)(j + 1) * DM + c]);
#pragma unroll
            for (int q = 0; q < 4; q++) {
                unsigned long long tp = *(const unsigned long long*)&T[g + 4 * q][j];
                ffma2(acc[q], tp, wp);
            }
        }
        float bb = ub2[c];
#pragma unroll
        for (int q = 0; q < 4; q++) {
            int i = g + 4 * q;
            size_t o = (size_t)(n0 + i) * DM + c;
            float2 a = unpack2(acc[q]);
            out[o] = h[o] + a.x + a.y + bb;
        }
    }
}

// ---------------- GraphNorm ----------------
__device__ __forceinline__ int lbound32(const int* a, int n, int key) {
    int lo = 0, hi = n;
    while (lo < hi) { int mid = (lo + hi) >> 1; if (a[mid] < key) lo = mid + 1; else hi = mid; }
    return lo;
}

__global__ __launch_bounds__(256) void graphnorm_kernel(
    const int* __restrict__ batch,
    const float* __restrict__ weight, const float* __restrict__ bias,
    const float* __restrict__ alpha, float* __restrict__ out)
{
    int gph = blockIdx.x;
    __shared__ int s_lo, s_hi;
    __shared__ float red[4][DM];
    if (threadIdx.x == 0) s_lo = lbound32(batch, NN, gph);
    if (threadIdx.x == 1) s_hi = lbound32(batch, NN, gph + 1);
    __syncthreads();
    int lo = s_lo, hi = s_hi;
    float fcnt = (float)max(hi - lo, 1);

    int c = threadIdx.x & 63;
    int r = threadIdx.x >> 6;

    float sum = 0.0f;
    for (int n = lo + r; n < hi; n += 4) sum += out[(size_t)n * DM + c];
    red[r][c] = sum;
    __syncthreads();
    float mean = (red[0][c] + red[1][c] + red[2][c] + red[3][c]) / fcnt;
    float am = alpha[c] * mean;
    __syncthreads();

    float sq = 0.0f;
    for (int n = lo + r; n < hi; n += 4) {
        float d = out[(size_t)n * DM + c] - am;
        sq += d * d;
    }
    red[r][c] = sq;
    __syncthreads();
    float var = (red[0][c] + red[1][c] + red[2][c] + red[3][c]) / fcnt;
    float istd = rsqrtf(var + EPS);
    float wv = weight[c], b = bias[c];

    for (int n = lo + r; n < hi; n += 4) {
        size_t o = (size_t)n * DM + c;
        out[o] = wv * (out[o] - am) * istd + b;
    }
}

// ---------------- launch ----------------
extern "C" void kernel_launch(void* const* d_in, const int* in_sizes, int n_in,
                              void* d_out, int out_size)
{
    (void)in_sizes; (void)n_in; (void)out_size;
    const float* h       = (const float*)d_in[0];
    const float* ea      = (const float*)d_in[1];
    const int*   eidx    = (const int*)d_in[2];
    const int*   batch   = (const int*)d_in[3];
    const float* msg_w1  = (const float*)d_in[4];
    const float* msg_b1  = (const float*)d_in[5];
    const float* msg_w2  = (const float*)d_in[6];
    const float* msg_b2  = (const float*)d_in[7];
    const float* upd_w1  = (const float*)d_in[8];
    const float* upd_b1  = (const float*)d_in[9];
    const float* upd_w2  = (const float*)d_in[10];
    const float* upd_b2  = (const float*)d_in[11];
    const float* gn_w    = (const float*)d_in[12];
    const float* gn_b    = (const float*)d_in[13];
    const float* gn_a    = (const float*)d_in[14];
    float* out = (float*)d_out;

    cudaFuncSetAttribute(edge_mma_kernel, cudaFuncAttributeMaxDynamicSharedMemorySize, SM_TOT);

    zero_agg_kernel<<<(NN * DM) / 256, 256>>>();
    transpose_w1<<<160, 256>>>(msg_w1);
    transpose_w2<<<64, 256>>>(msg_w2);
    edge_mma_kernel<<<NE / 128, 256, SM_TOT>>>(h, ea, eidx, msg_b1, msg_b2);
    node_kernel<<<NN / 16, 256>>>(h, upd_w1, upd_b1, upd_w2, upd_b2, out);
    graphnorm_kernel<<<NG, 256>>>(batch, gn_w, gn_b, gn_a, out);
}

// round 7
// speedup vs baseline: 1.2522x; 1.0065x over previous
#include <cuda_runtime.h>
#include <cstdint>

// Problem constants
#define NN 50000
#define NE 800000
#define DM 64
#define DE 32
#define DH 256
#define NG 64
#define EPS 1e-5f

// ---------------- scratch ----------------
__device__ float    g_agg[(size_t)NN * DM];
__device__ unsigned g_w1t[256 * 160];   // W1^T tf32 bits: [n][k]   (k = 160 input dims)
__device__ unsigned g_w2t[64 * 256];    // W2^T tf32 bits: [c][j]

// ---------------- helpers ----------------
__device__ __forceinline__ unsigned tf32u(float x) {
    unsigned u;
    asm("cvt.rna.tf32.f32 %0, %1;" : "=r"(u) : "f"(x));
    return u;
}
__device__ __forceinline__ float silu(float t) { return t / (1.0f + __expf(-t)); }

// mma.sync m16n8k8 tf32 (baseline PTX, works on plain sm_103 target -> fallback HMMA)
__device__ __forceinline__ void mma_tf32(float& d0, float& d1, float& d2, float& d3,
                                         unsigned a0, unsigned a1, unsigned a2, unsigned a3,
                                         unsigned b0, unsigned b1) {
    asm volatile(
        "mma.sync.aligned.m16n8k8.row.col.f32.tf32.tf32.f32 "
        "{%0,%1,%2,%3}, {%4,%5,%6,%7}, {%8,%9}, {%0,%1,%2,%3};"
        : "+f"(d0), "+f"(d1), "+f"(d2), "+f"(d3)
        : "r"(a0), "r"(a1), "r"(a2), "r"(a3), "r"(b0), "r"(b1));
}

// f32x2 helpers for the FFMA node kernel
__device__ __forceinline__ void ffma2(unsigned long long &acc, unsigned long long a, unsigned long long b) {
    asm("fma.rn.f32x2 %0, %1, %2, %0;" : "+l"(acc) : "l"(a), "l"(b));
}
__device__ __forceinline__ unsigned long long pack2(float lo, float hi) {
    unsigned long long r;
    asm("mov.b64 %0, {%1, %2};" : "=l"(r) : "f"(lo), "f"(hi));
    return r;
}
__device__ __forceinline__ float2 unpack2(unsigned long long v) {
    float2 f;
    asm("mov.b64 {%0, %1}, %2;" : "=f"(f.x), "=f"(f.y) : "l"(v));
    return f;
}

// ---------------- kernel 0: zero agg ----------------
__global__ void zero_agg_kernel() {
    int i = blockIdx.x * blockDim.x + threadIdx.x;
    if (i < NN * DM) g_agg[i] = 0.0f;
}

// ---------------- weight transposes + tf32 rounding (tiny) ----------------
__global__ void transpose_w1(const float* __restrict__ w1) {
    int k = blockIdx.x;        // 0..159
    int n = threadIdx.x;       // 0..255
    g_w1t[(size_t)n * 160 + k] = tf32u(w1[(size_t)k * 256 + n]);
}
__global__ void transpose_w2(const float* __restrict__ w2) {
    int c = blockIdx.x;        // 0..63
    int j = threadIdx.x;       // 0..255
    g_w2t[(size_t)c * 256 + j] = tf32u(w2[(size_t)j * 64 + c]);
}

// ---------------- edge MLP via mma.sync tf32 ----------------
// Block: 128 edges, 256 threads (8 warps; warp w -> rows 16w..16w+15).
// Shared layout (bytes), strides padded for conflict-free fragment LDS:
//   sA  [128][164] tf32   A = [h_dst | h_src | ea]
//   sW1 [64][164]  tf32   W1^T chunk (64 output cols x 160 k)
//   sT  [128][68]  tf32   silu hidden chunk
//   sW2 [64][68]   tf32   W2^T chunk (64 out x 64 k-chunk)
#define SM_DST 0
#define SM_SRC 512
#define SM_B1  1024
#define SM_B2  2048
#define SM_A   2560
#define SM_W1  86528
#define SM_T   128512
#define SM_W2  163328
#define SM_TOT 180736

__global__ __launch_bounds__(256, 1) void edge_mma_kernel(
    const float* __restrict__ h, const float* __restrict__ ea,
    const int* __restrict__ eidx,
    const float* __restrict__ b1, const float* __restrict__ b2)
{
    extern __shared__ char smem[];
    int*      s_dst = (int*)(smem + SM_DST);
    int*      s_src = (int*)(smem + SM_SRC);
    float*    s_b1  = (float*)(smem + SM_B1);
    float*    s_b2  = (float*)(smem + SM_B2);
    unsigned* sA    = (unsigned*)(smem + SM_A);
    unsigned* sW1   = (unsigned*)(smem + SM_W1);
    unsigned* sT    = (unsigned*)(smem + SM_T);
    unsigned* sW2   = (unsigned*)(smem + SM_W2);

    const int tid = threadIdx.x;
    const int w   = tid >> 5;
    const int lane = tid & 31;
    const int r4 = lane >> 2;       // 0..7
    const int c4 = lane & 3;        // 0..3
    const int e0 = blockIdx.x * 128;

    if (tid < 128) s_dst[tid] = eidx[NE + e0 + tid];          // edge_index[1] = dst
    else           s_src[tid - 128] = eidx[e0 + tid - 128];   // edge_index[0] = src
    s_b1[tid] = b1[tid];
    if (tid < 64) s_b2[tid] = b2[tid];
    __syncthreads();

    // ---- gather A tile [128 x 160] tf32 ----
    for (int idx = tid; idx < 128 * 40; idx += 256) {
        int r = idx / 40, cc = (idx % 40) * 4;
        const float4* src;
        if (cc < 64)       src = (const float4*)(h + (size_t)s_dst[r] * 64 + cc);
        else if (cc < 128) src = (const float4*)(h + (size_t)s_src[r] * 64 + (cc - 64));
        else               src = (const float4*)(ea + (size_t)(e0 + r) * 32 + (cc - 128));
        float4 v = *src;
        uint4 u;
        u.x = tf32u(v.x); u.y = tf32u(v.y); u.z = tf32u(v.z); u.w = tf32u(v.w);
        *(uint4*)(sA + r * 164 + cc) = u;
    }

    const int R0 = 16 * w;
    float acc2[8][4];
#pragma unroll
    for (int t = 0; t < 8; t++)
#pragma unroll
        for (int j = 0; j < 4; j++) acc2[t][j] = 0.0f;

    const unsigned* pa  = sA + (R0 + r4) * 164 + c4;   // GEMM1 A base (rows +0 / +8 via +8*164)
    const unsigned* pt  = sT + (R0 + r4) * 68 + c4;    // GEMM2 A base

    for (int q = 0; q < 4; q++) {
        __syncthreads();   // previous chunk's readers done before overwrite
        // load W1^T chunk [64 x 160]
        for (int idx = tid; idx < 64 * 40; idx += 256) {
            int nl = idx / 40, cc = (idx % 40) * 4;
            *(uint4*)(sW1 + nl * 164 + cc) =
                *(const uint4*)(g_w1t + (size_t)(q * 64 + nl) * 160 + cc);
        }
        // load W2^T chunk [64 x 64] (k = cols 64q..64q+63)
        for (int idx = tid; idx < 64 * 16; idx += 256) {
            int c = idx / 16, j4 = (idx % 16) * 4;
            *(uint4*)(sW2 + c * 68 + j4) =
                *(const uint4*)(g_w2t + (size_t)c * 256 + q * 64 + j4);
        }
        __syncthreads();

        // ---- GEMM1: D1chunk[16x64 per warp] = A[16x160] @ W1t_chunk ----
        float acc1[8][4];
#pragma unroll
        for (int t = 0; t < 8; t++)
#pragma unroll
            for (int j = 0; j < 4; j++) acc1[t][j] = 0.0f;

        for (int ks = 0; ks < 20; ks++) {
            int k0 = ks * 8;
            unsigned a0 = pa[k0],            a2 = pa[k0 + 4];
            unsigned a1 = pa[8 * 164 + k0],  a3 = pa[8 * 164 + k0 + 4];
#pragma unroll
            for (int t = 0; t < 8; t++) {
                const unsigned* pb = sW1 + (8 * t + r4) * 164 + c4;
                mma_tf32(acc1[t][0], acc1[t][1], acc1[t][2], acc1[t][3],
                         a0, a1, a2, a3, pb[k0], pb[k0 + 4]);
            }
        }

        // ---- +b1, silu, tf32 -> sT (own rows only) ----
#pragma unroll
        for (int t = 0; t < 8; t++) {
            int col = 8 * t + 2 * c4;
            int gc  = 64 * q + col;
            float bb0 = s_b1[gc], bb1 = s_b1[gc + 1];
            uint2 lo, hi;
            lo.x = tf32u(silu(acc1[t][0] + bb0));
            lo.y = tf32u(silu(acc1[t][1] + bb1));
            hi.x = tf32u(silu(acc1[t][2] + bb0));
            hi.y = tf32u(silu(acc1[t][3] + bb1));
            *(uint2*)(sT + (R0 + r4) * 68 + col)       = lo;
            *(uint2*)(sT + (R0 + 8 + r4) * 68 + col)   = hi;
        }
        __syncwarp();

        // ---- GEMM2 partial: acc2 += Tchunk[16x64] @ W2t_chunk ----
        for (int kc = 0; kc < 8; kc++) {
            int k0 = kc * 8;
            unsigned a0 = pt[k0],           a2 = pt[k0 + 4];
            unsigned a1 = pt[8 * 68 + k0],  a3 = pt[8 * 68 + k0 + 4];
#pragma unroll
            for (int t = 0; t < 8; t++) {
                const unsigned* pb = sW2 + (8 * t + r4) * 68 + c4;
                mma_tf32(acc2[t][0], acc2[t][1], acc2[t][2], acc2[t][3],
                         a0, a1, a2, a3, pb[k0], pb[k0 + 4]);
            }
        }
        __syncwarp();
    }

    // ---- epilogue: +b2, vectorized reduction scatter into g_agg ----
    {
        int row0 = R0 + r4, row1 = R0 + 8 + r4;
        int d0i = s_dst[row0], d1i = s_dst[row1];
#pragma unroll
        for (int t = 0; t < 8; t++) {
            int col = 8 * t + 2 * c4;
            float bb0 = s_b2[col], bb1 = s_b2[col + 1];
            float x0 = acc2[t][0] + bb0, x1 = acc2[t][1] + bb1;
            float x2 = acc2[t][2] + bb0, x3 = acc2[t][3] + bb1;
            asm volatile("red.global.add.v2.f32 [%0], {%1,%2};"
                         :: "l"(g_agg + (size_t)d0i * 64 + col), "f"(x0), "f"(x1) : "memory");
            asm volatile("red.global.add.v2.f32 [%0], {%1,%2};"
                         :: "l"(g_agg + (size_t)d1i * 64 + col), "f"(x2), "f"(x3) : "memory");
        }
    }
}

// ---------------- node update MLP + residual (FFMA f32x2, known-good) ----------------
__global__ __launch_bounds__(256) void node_kernel(
    const float* __restrict__ h,
    const float* __restrict__ uw1, const float* __restrict__ ub1,
    const float* __restrict__ uw2, const float* __restrict__ ub2,
    float* __restrict__ out)
{
    const int NT = 16;
    __shared__ __align__(16) unsigned long long ins2[NT][2 * DM];
    __shared__ __align__(16) float T[NT][DH];
    int tid = threadIdx.x;
    int n0 = blockIdx.x * NT;

    for (int idx = tid; idx < NT * 2 * DM; idx += 256) {
        int i = idx / (2 * DM), k = idx % (2 * DM);
        float v = (k < DM) ? h[(size_t)(n0 + i) * DM + k]
                           : g_agg[(size_t)(n0 + i) * DM + (k - DM)];
        ins2[i][k] = pack2(v, v);
    }
    __syncthreads();

    {
        int cp = tid & 127;
        int hg = tid >> 7;
        unsigned long long bpair = *(const unsigned long long*)(ub1 + 2 * cp);
        unsigned long long acc[8];
#pragma unroll
        for (int ii = 0; ii < 8; ii++) acc[ii] = bpair;
        for (int k = 0; k < 2 * DM; k++) {
            unsigned long long wv = *(const unsigned long long*)(uw1 + (size_t)k * DH + 2 * cp);
#pragma unroll
            for (int ii = 0; ii < 8; ii++) ffma2(acc[ii], ins2[hg * 8 + ii][k], wv);
        }
#pragma unroll
        for (int ii = 0; ii < 8; ii++) {
            int i = hg * 8 + ii;
            float2 t = unpack2(acc[ii]);
            T[i][2 * cp]     = silu(t.x);
            T[i][2 * cp + 1] = silu(t.y);
        }
    }
    __syncthreads();

    {
        int c = tid & 63;
        int g = tid >> 6;
        unsigned long long acc[4] = {0ull, 0ull, 0ull, 0ull};
#pragma unroll 8
        for (int j = 0; j < DH; j += 2) {
            unsigned long long wp = pack2(uw2[(size_t)j * DM + c], uw2[(size_t)(j + 1) * DM + c]);
#pragma unroll
            for (int q = 0; q < 4; q++) {
                unsigned long long tp = *(const unsigned long long*)&T[g + 4 * q][j];
                ffma2(acc[q], tp, wp);
            }
        }
        float bb = ub2[c];
#pragma unroll
        for (int q = 0; q < 4; q++) {
            int i = g + 4 * q;
            size_t o = (size_t)(n0 + i) * DM + c;
            float2 a = unpack2(acc[q]);
            out[o] = h[o] + a.x + a.y + bb;
        }
    }
}

// ---------------- GraphNorm ----------------
__device__ __forceinline__ int lbound32(const int* a, int n, int key) {
    int lo = 0, hi = n;
    while (lo < hi) { int mid = (lo + hi) >> 1; if (a[mid] < key) lo = mid + 1; else hi = mid; }
    return lo;
}

__global__ __launch_bounds__(256) void graphnorm_kernel(
    const int* __restrict__ batch,
    const float* __restrict__ weight, const float* __restrict__ bias,
    const float* __restrict__ alpha, float* __restrict__ out)
{
    int gph = blockIdx.x;
    __shared__ int s_lo, s_hi;
    __shared__ float red[4][DM];
    if (threadIdx.x == 0) s_lo = lbound32(batch, NN, gph);
    if (threadIdx.x == 1) s_hi = lbound32(batch, NN, gph + 1);
    __syncthreads();
    int lo = s_lo, hi = s_hi;
    float fcnt = (float)max(hi - lo, 1);

    int c = threadIdx.x & 63;
    int r = threadIdx.x >> 6;

    float sum = 0.0f;
    for (int n = lo + r; n < hi; n += 4) sum += out[(size_t)n * DM + c];
    red[r][c] = sum;
    __syncthreads();
    float mean = (red[0][c] + red[1][c] + red[2][c] + red[3][c]) / fcnt;
    float am = alpha[c] * mean;
    __syncthreads();

    float sq = 0.0f;
    for (int n = lo + r; n < hi; n += 4) {
        float d = out[(size_t)n * DM + c] - am;
        sq += d * d;
    }
    red[r][c] = sq;
    __syncthreads();
    float var = (red[0][c] + red[1][c] + red[2][c] + red[3][c]) / fcnt;
    float istd = rsqrtf(var + EPS);
    float wv = weight[c], b = bias[c];

    for (int n = lo + r; n < hi; n += 4) {
        size_t o = (size_t)n * DM + c;
        out[o] = wv * (out[o] - am) * istd + b;
    }
}

// ---------------- launch ----------------
extern "C" void kernel_launch(void* const* d_in, const int* in_sizes, int n_in,
                              void* d_out, int out_size)
{
    (void)in_sizes; (void)n_in; (void)out_size;
    const float* h       = (const float*)d_in[0];
    const float* ea      = (const float*)d_in[1];
    const int*   eidx    = (const int*)d_in[2];
    const int*   batch   = (const int*)d_in[3];
    const float* msg_w1  = (const float*)d_in[4];
    const float* msg_b1  = (const float*)d_in[5];
    const float* msg_w2  = (const float*)d_in[6];
    const float* msg_b2  = (const float*)d_in[7];
    const float* upd_w1  = (const float*)d_in[8];
    const float* upd_b1  = (const float*)d_in[9];
    const float* upd_w2  = (const float*)d_in[10];
    const float* upd_b2  = (const float*)d_in[11];
    const float* gn_w    = (const float*)d_in[12];
    const float* gn_b    = (const float*)d_in[13];
    const float* gn_a    = (const float*)d_in[14];
    float* out = (float*)d_out;

    cudaFuncSetAttribute(edge_mma_kernel, cudaFuncAttributeMaxDynamicSharedMemorySize, SM_TOT);

    zero_agg_kernel<<<(NN * DM) / 256, 256>>>();
    transpose_w1<<<160, 256>>>(msg_w1);
    transpose_w2<<<64, 256>>>(msg_w2);
    edge_mma_kernel<<<NE / 128, 256, SM_TOT>>>(h, ea, eidx, msg_b1, msg_b2);
    node_kernel<<<NN / 16, 256>>>(h, upd_w1, upd_b1, upd_w2, upd_b2, out);
    graphnorm_kernel<<<NG, 256>>>(batch, gn_w, gn_b, gn_a, out);
}

// round 9
// speedup vs baseline: 3.0325x; 2.4218x over previous
#include <cuda_runtime.h>
#include <cstdint>

#define NN 50000
#define NE 800000
#define NG 64
#define EPS 1e-5f

// ---------------- scratch ----------------
__device__ float    g_P[(size_t)NN * 768];  // [0:256) msg dst-proj+b1 | [256:512) msg src-proj | [512:768) upd h-proj+ub1
__device__ float    g_agg[(size_t)NN * 64];
__device__ unsigned g_w1et[256 * 32];       // msg W1 edge rows, transposed [n][k], tf32
__device__ unsigned g_w2t[64 * 256];        // msg W2^T [c][j]
__device__ unsigned g_wPt[768 * 64];        // P weights^T [o][k]
__device__ float    g_bP[768];
__device__ unsigned g_uw1at[256 * 64];      // upd W1 agg rows ^T
__device__ unsigned g_uw2t[64 * 256];       // upd W2^T

__device__ __forceinline__ unsigned tf32u(float x) {
    unsigned u; asm("cvt.rna.tf32.f32 %0, %1;" : "=r"(u) : "f"(x)); return u;
}
__device__ __forceinline__ float silu(float t) { return t / (1.0f + __expf(-t)); }
__device__ __forceinline__ void mma_tf32(float& d0, float& d1, float& d2, float& d3,
                                         unsigned a0, unsigned a1, unsigned a2, unsigned a3,
                                         unsigned b0, unsigned b1) {
    asm volatile("mma.sync.aligned.m16n8k8.row.col.f32.tf32.tf32.f32 "
                 "{%0,%1,%2,%3}, {%4,%5,%6,%7}, {%8,%9}, {%0,%1,%2,%3};"
                 : "+f"(d0), "+f"(d1), "+f"(d2), "+f"(d3)
                 : "r"(a0), "r"(a1), "r"(a2), "r"(a3), "r"(b0), "r"(b1));
}

// ---------------- prep ----------------
__global__ void zero_agg_kernel() {
    int i = blockIdx.x * blockDim.x + threadIdx.x;
    if (i < NN * 64) g_agg[i] = 0.0f;
}
__global__ void prep_w1et(const float* __restrict__ w1) {          // <<<256,32>>>
    int n = blockIdx.x, k = threadIdx.x;
    g_w1et[n * 32 + k] = tf32u(w1[(size_t)(128 + k) * 256 + n]);
}
__global__ void prep_w2t(const float* __restrict__ w2) {           // <<<64,256>>>
    int c = blockIdx.x, j = threadIdx.x;
    g_w2t[c * 256 + j] = tf32u(w2[(size_t)j * 64 + c]);
}
__global__ void prep_wPt(const float* __restrict__ mw1, const float* __restrict__ uw1,
                         const float* __restrict__ mb1, const float* __restrict__ ub1) { // <<<768,64>>>
    int o = blockIdx.x, k = threadIdx.x;
    float v;
    if (o < 256)      v = mw1[(size_t)k * 256 + o];
    else if (o < 512) v = mw1[(size_t)(64 + k) * 256 + (o - 256)];
    else              v = uw1[(size_t)k * 256 + (o - 512)];
    g_wPt[o * 64 + k] = tf32u(v);
    if (k == 0) g_bP[o] = (o < 256) ? mb1[o] : (o < 512 ? 0.0f : ub1[o - 512]);
}
__global__ void prep_uw1at(const float* __restrict__ uw1) {        // <<<256,64>>>
    int n = blockIdx.x, k = threadIdx.x;
    g_uw1at[n * 64 + k] = tf32u(uw1[(size_t)(64 + k) * 256 + n]);
}
__global__ void prep_uw2t(const float* __restrict__ uw2) {         // <<<64,256>>>
    int c = blockIdx.x, j = threadIdx.x;
    g_uw2t[c * 256 + j] = tf32u(uw2[(size_t)j * 64 + c]);
}

// ---------------- P kernel: g_P[n] = h[n] @ Wp + bP ----------------
#define SMEM_P ((128 * 68 + 64 * 68) * 4)
__global__ __launch_bounds__(256) void p_kernel(const float* __restrict__ h) {
    extern __shared__ unsigned sm[];
    unsigned* sH = sm;                // [128][68]
    unsigned* sW = sm + 128 * 68;     // [64][68]
    int tid = threadIdx.x, w = tid >> 5, lane = tid & 31;
    int r4 = lane >> 2, c4 = lane & 3, n0 = blockIdx.x * 128, R0 = 16 * w;

    for (int i = tid; i < 128 * 16; i += 256) {
        int r = i >> 4, j4 = (i & 15) * 4;
        int n = n0 + r; if (n >= NN) n = NN - 1;
        float4 v = *(const float4*)(h + (size_t)n * 64 + j4);
        uint4 u = {tf32u(v.x), tf32u(v.y), tf32u(v.z), tf32u(v.w)};
        *(uint4*)(sH + r * 68 + j4) = u;
    }
#pragma unroll 1
    for (int q = 0; q < 12; q++) {
        __syncthreads();
        for (int i = tid; i < 64 * 16; i += 256) {
            int r = i >> 4, j4 = (i & 15) * 4;
            *(uint4*)(sW + r * 68 + j4) = *(const uint4*)(g_wPt + (size_t)(q * 64 + r) * 64 + j4);
        }
        __syncthreads();
        int cb = 64 * q + 2 * c4;
        float acc[8][4];
#pragma unroll
        for (int t = 0; t < 8; t++) {
            float2 bb = *(const float2*)(g_bP + cb + 8 * t);
            acc[t][0] = bb.x; acc[t][1] = bb.y; acc[t][2] = bb.x; acc[t][3] = bb.y;
        }
#pragma unroll
        for (int ks = 0; ks < 8; ks++) {
            int k0 = 8 * ks;
            unsigned a0 = sH[(R0 + r4) * 68 + c4 + k0];
            unsigned a1 = sH[(R0 + 8 + r4) * 68 + c4 + k0];
            unsigned a2 = sH[(R0 + r4) * 68 + c4 + 4 + k0];
            unsigned a3 = sH[(R0 + 8 + r4) * 68 + c4 + 4 + k0];
#pragma unroll
            for (int t = 0; t < 8; t++) {
                const unsigned* pb = sW + (8 * t + r4) * 68 + c4;
                mma_tf32(acc[t][0], acc[t][1], acc[t][2], acc[t][3], a0, a1, a2, a3, pb[k0], pb[k0 + 4]);
            }
        }
        int na = n0 + R0 + r4, nb = na + 8;
#pragma unroll
        for (int t = 0; t < 8; t++) {
            int col = cb + 8 * t;
            if (na < NN) *(float2*)(g_P + (size_t)na * 768 + col) = make_float2(acc[t][0], acc[t][1]);
            if (nb < NN) *(float2*)(g_P + (size_t)nb * 768 + col) = make_float2(acc[t][2], acc[t][3]);
        }
    }
}

// ---------------- edge kernel: persistent, warp-independent 16-edge tiles ----------------
// u32 offsets: W1E[256][36]@0  W2[64][260]@9216  EA 12x[16][36]@25856  T 12x[16][68]@32768
#define SMEM_E (45824 * 4)
__global__ __launch_bounds__(384, 1) void edge_kernel(
    const float* __restrict__ ea, const int* __restrict__ eidx, const float* __restrict__ b2)
{
    extern __shared__ unsigned sm[];
    unsigned* sW1e = sm;
    unsigned* sW2  = sm + 9216;
    int tid = threadIdx.x, w = tid >> 5, lane = tid & 31;
    int r4 = lane >> 2, c4 = lane & 3;
    unsigned* sEA = sm + 25856 + w * (16 * 36);
    unsigned* sT  = sm + 32768 + w * (16 * 68);

    for (int i = tid; i < 256 * 8; i += 384) {
        int n = i >> 3, j4 = (i & 7) * 4;
        *(uint4*)(sW1e + n * 36 + j4) = *(const uint4*)(g_w1et + n * 32 + j4);
    }
    for (int i = tid; i < 64 * 64; i += 384) {
        int c = i >> 6, j4 = (i & 63) * 4;
        *(uint4*)(sW2 + c * 260 + j4) = *(const uint4*)(g_w2t + c * 256 + j4);
    }
    float2 b2c[8];
#pragma unroll
    for (int t = 0; t < 8; t++) b2c[t] = *(const float2*)(b2 + 8 * t + 2 * c4);
    __syncthreads();

    const int nw = gridDim.x * 12;
#pragma unroll 1
    for (int tile = blockIdx.x * 12 + w; tile < NE / 16; tile += nw) {
        int e0 = tile * 16;
        int my = (lane < 16) ? eidx[NE + e0 + lane] : eidx[e0 + lane - 16];  // dst | src
        int d0 = __shfl_sync(0xffffffffu, my, r4);
        int d1 = __shfl_sync(0xffffffffu, my, 8 + r4);
        int s0 = __shfl_sync(0xffffffffu, my, 16 + r4);
        int s1 = __shfl_sync(0xffffffffu, my, 24 + r4);
        __syncwarp();
        {   // stage ea tile (16 x 32) tf32
            int row = lane >> 1, cc = (lane & 1) * 16;
            const float4* srcp = (const float4*)(ea + (size_t)(e0 + row) * 32 + cc);
#pragma unroll
            for (int i = 0; i < 4; i++) {
                float4 v = srcp[i];
                uint4 u = {tf32u(v.x), tf32u(v.y), tf32u(v.z), tf32u(v.w)};
                *(uint4*)(sEA + row * 36 + cc + 4 * i) = u;
            }
        }
        __syncwarp();
        const float* Pd0 = g_P + (size_t)d0 * 768;
        const float* Pd1 = g_P + (size_t)d1 * 768;
        const float* Ps0 = g_P + (size_t)s0 * 768 + 256;
        const float* Ps1 = g_P + (size_t)s1 * 768 + 256;

        float acc2[8][4];
#pragma unroll
        for (int t = 0; t < 8; t++) { acc2[t][0]=acc2[t][1]=acc2[t][2]=acc2[t][3]=0.0f; }

#pragma unroll 1
        for (int q = 0; q < 4; q++) {
            int cb = 64 * q + 2 * c4;
            float acc1[8][4];
#pragma unroll
            for (int t = 0; t < 8; t++) {   // init: P_dst + P_src
                float2 pa = *(const float2*)(Pd0 + cb + 8 * t);
                float2 pb = *(const float2*)(Ps0 + cb + 8 * t);
                float2 pc = *(const float2*)(Pd1 + cb + 8 * t);
                float2 pd = *(const float2*)(Ps1 + cb + 8 * t);
                acc1[t][0] = pa.x + pb.x; acc1[t][1] = pa.y + pb.y;
                acc1[t][2] = pc.x + pd.x; acc1[t][3] = pc.y + pd.y;
            }
#pragma unroll
            for (int ks = 0; ks < 4; ks++) {   // + ea @ W1e (k=32)
                int k0 = 8 * ks;
                unsigned a0 = sEA[r4 * 36 + c4 + k0];
                unsigned a1 = sEA[(8 + r4) * 36 + c4 + k0];
                unsigned a2 = sEA[r4 * 36 + c4 + 4 + k0];
                unsigned a3 = sEA[(8 + r4) * 36 + c4 + 4 + k0];
#pragma unroll
                for (int t = 0; t < 8; t++) {
                    const unsigned* pb = sW1e + (64 * q + 8 * t + r4) * 36 + c4;
                    mma_tf32(acc1[t][0], acc1[t][1], acc1[t][2], acc1[t][3], a0, a1, a2, a3, pb[k0], pb[k0 + 4]);
                }
            }
#pragma unroll
            for (int t = 0; t < 8; t++) {   // silu -> warp-private sT
                int col = 8 * t + 2 * c4;
                uint2 lo = {tf32u(silu(acc1[t][0])), tf32u(silu(acc1[t][1]))};
                uint2 hi = {tf32u(silu(acc1[t][2])), tf32u(silu(acc1[t][3]))};
                *(uint2*)(sT + r4 * 68 + col) = lo;
                *(uint2*)(sT + (8 + r4) * 68 + col) = hi;
            }
            __syncwarp();
#pragma unroll
            for (int kc = 0; kc < 8; kc++) {   // acc2 += T_chunk @ W2_chunk
                int k0 = 8 * kc;
                unsigned a0 = sT[r4 * 68 + c4 + k0];
                unsigned a1 = sT[(8 + r4) * 68 + c4 + k0];
                unsigned a2 = sT[r4 * 68 + c4 + 4 + k0];
                unsigned a3 = sT[(8 + r4) * 68 + c4 + 4 + k0];
#pragma unroll
                for (int t = 0; t < 8; t++) {
                    const unsigned* pb = sW2 + (8 * t + r4) * 260 + 64 * q + c4;
                    mma_tf32(acc2[t][0], acc2[t][1], acc2[t][2], acc2[t][3], a0, a1, a2, a3, pb[k0], pb[k0 + 4]);
                }
            }
            __syncwarp();
        }
        float* A0 = g_agg + (size_t)d0 * 64;
        float* A1 = g_agg + (size_t)d1 * 64;
#pragma unroll
        for (int t = 0; t < 8; t++) {
            int col = 8 * t + 2 * c4;
            float x0 = acc2[t][0] + b2c[t].x, x1 = acc2[t][1] + b2c[t].y;
            float x2 = acc2[t][2] + b2c[t].x, x3 = acc2[t][3] + b2c[t].y;
            asm volatile("red.global.add.v2.f32 [%0], {%1,%2};" :: "l"(A0 + col), "f"(x0), "f"(x1) : "memory");
            asm volatile("red.global.add.v2.f32 [%0], {%1,%2};" :: "l"(A1 + col), "f"(x2), "f"(x3) : "memory");
        }
    }
}

// ---------------- node kernel: persistent, warp-independent 16-node tiles ----------------
// u32 offsets: UW1A[256][68]@0  UW2[64][260]@17408  AG 8x[16][68]@34048  T 8x[16][68]@42752
#define SMEM_N (51456 * 4)
__global__ __launch_bounds__(256, 1) void node_kernel(
    const float* __restrict__ h, const float* __restrict__ ub2, float* __restrict__ out)
{
    extern __shared__ unsigned sm[];
    unsigned* sW1 = sm;
    unsigned* sW2 = sm + 17408;
    int tid = threadIdx.x, w = tid >> 5, lane = tid & 31;
    int r4 = lane >> 2, c4 = lane & 3;
    unsigned* sAG = sm + 34048 + w * (16 * 68);
    unsigned* sT  = sm + 42752 + w * (16 * 68);

    for (int i = tid; i < 256 * 16; i += 256) {
        int n = i >> 4, j4 = (i & 15) * 4;
        *(uint4*)(sW1 + n * 68 + j4) = *(const uint4*)(g_uw1at + n * 64 + j4);
    }
    for (int i = tid; i < 64 * 64; i += 256) {
        int c = i >> 6, j4 = (i & 63) * 4;
        *(uint4*)(sW2 + c * 260 + j4) = *(const uint4*)(g_uw2t + c * 256 + j4);
    }
    float2 bc[8];
#pragma unroll
    for (int t = 0; t < 8; t++) bc[t] = *(const float2*)(ub2 + 8 * t + 2 * c4);
    __syncthreads();

    const int nw = gridDim.x * 8;
#pragma unroll 1
    for (int tile = blockIdx.x * 8 + w; tile < NN / 16; tile += nw) {
        int n0 = tile * 16;
        {   // stage agg tile (16 x 64) tf32
            int row = lane >> 1, cc = (lane & 1) * 32;
            const float4* srcp = (const float4*)(g_agg + (size_t)(n0 + row) * 64 + cc);
#pragma unroll
            for (int i = 0; i < 8; i++) {
                float4 v = srcp[i];
                uint4 u = {tf32u(v.x), tf32u(v.y), tf32u(v.z), tf32u(v.w)};
                *(uint4*)(sAG + row * 68 + cc + 4 * i) = u;
            }
        }
        __syncwarp();
        const float* Pu0 = g_P + (size_t)(n0 + r4) * 768 + 512;
        const float* Pu1 = g_P + (size_t)(n0 + 8 + r4) * 768 + 512;

        float acc2[8][4];
#pragma unroll
        for (int t = 0; t < 8; t++) { acc2[t][0]=acc2[t][1]=acc2[t][2]=acc2[t][3]=0.0f; }

#pragma unroll 1
        for (int q = 0; q < 4; q++) {
            int cb = 64 * q + 2 * c4;
            float acc1[8][4];
#pragma unroll
            for (int t = 0; t < 8; t++) {
                float2 pa = *(const float2*)(Pu0 + cb + 8 * t);
                float2 pc = *(const float2*)(Pu1 + cb + 8 * t);
                acc1[t][0] = pa.x; acc1[t][1] = pa.y; acc1[t][2] = pc.x; acc1[t][3] = pc.y;
            }
#pragma unroll
            for (int ks = 0; ks < 8; ks++) {   // + agg @ Uw1a (k=64)
                int k0 = 8 * ks;
                unsigned a0 = sAG[r4 * 68 + c4 + k0];
                unsigned a1 = sAG[(8 + r4) * 68 + c4 + k0];
                unsigned a2 = sAG[r4 * 68 + c4 + 4 + k0];
                unsigned a3 = sAG[(8 + r4) * 68 + c4 + 4 + k0];
#pragma unroll
                for (int t = 0; t < 8; t++) {
                    const unsigned* pb = sW1 + (64 * q + 8 * t + r4) * 68 + c4;
                    mma_tf32(acc1[t][0], acc1[t][1], acc1[t][2], acc1[t][3], a0, a1, a2, a3, pb[k0], pb[k0 + 4]);
                }
            }
#pragma unroll
            for (int t = 0; t < 8; t++) {
                int col = 8 * t + 2 * c4;
                uint2 lo = {tf32u(silu(acc1[t][0])), tf32u(silu(acc1[t][1]))};
                uint2 hi = {tf32u(silu(acc1[t][2])), tf32u(silu(acc1[t][3]))};
                *(uint2*)(sT + r4 * 68 + col) = lo;
                *(uint2*)(sT + (8 + r4) * 68 + col) = hi;
            }
            __syncwarp();
#pragma unroll
            for (int kc = 0; kc < 8; kc++) {
                int k0 = 8 * kc;
                unsigned a0 = sT[r4 * 68 + c4 + k0];
                unsigned a1 = sT[(8 + r4) * 68 + c4 + k0];
                unsigned a2 = sT[r4 * 68 + c4 + 4 + k0];
                unsigned a3 = sT[(8 + r4) * 68 + c4 + 4 + k0];
#pragma unroll
                for (int t = 0; t < 8; t++) {
                    const unsigned* pb = sW2 + (8 * t + r4) * 260 + 64 * q + c4;
                    mma_tf32(acc2[t][0], acc2[t][1], acc2[t][2], acc2[t][3], a0, a1, a2, a3, pb[k0], pb[k0 + 4]);
                }
            }
            __syncwarp();
        }
        int na = n0 + r4, nb = n0 + 8 + r4;
#pragma unroll
        for (int t = 0; t < 8; t++) {   // residual + bias
            int col = 8 * t + 2 * c4;
            float2 h0 = *(const float2*)(h + (size_t)na * 64 + col);
            float2 h1 = *(const float2*)(h + (size_t)nb * 64 + col);
            *(float2*)(out + (size_t)na * 64 + col) =
                make_float2(h0.x + acc2[t][0] + bc[t].x, h0.y + acc2[t][1] + bc[t].y);
            *(float2*)(out + (size_t)nb * 64 + col) =
                make_float2(h1.x + acc2[t][2] + bc[t].x, h1.y + acc2[t][3] + bc[t].y);
        }
    }
}

// ---------------- GraphNorm ----------------
__device__ __forceinline__ int lbound32(const int* a, int n, int key) {
    int lo = 0, hi = n;
    while (lo < hi) { int mid = (lo + hi) >> 1; if (a[mid] < key) lo = mid + 1; else hi = mid; }
    return lo;
}
__global__ __launch_bounds__(256) void graphnorm_kernel(
    const int* __restrict__ batch, const float* __restrict__ weight,
    const float* __restrict__ bias, const float* __restrict__ alpha, float* __restrict__ out)
{
    int gph = blockIdx.x;
    __shared__ int s_lo, s_hi;
    __shared__ float red[4][64];
    if (threadIdx.x == 0) s_lo = lbound32(batch, NN, gph);
    if (threadIdx.x == 1) s_hi = lbound32(batch, NN, gph + 1);
    __syncthreads();
    int lo = s_lo, hi = s_hi;
    float fcnt = (float)max(hi - lo, 1);
    int c = threadIdx.x & 63, r = threadIdx.x >> 6;

    float sum = 0.0f;
    for (int n = lo + r; n < hi; n += 4) sum += out[(size_t)n * 64 + c];
    red[r][c] = sum;
    __syncthreads();
    float mean = (red[0][c] + red[1][c] + red[2][c] + red[3][c]) / fcnt;
    float am = alpha[c] * mean;
    __syncthreads();

    float sq = 0.0f;
    for (int n = lo + r; n < hi; n += 4) { float d = out[(size_t)n * 64 + c] - am; sq += d * d; }
    red[r][c] = sq;
    __syncthreads();
    float var = (red[0][c] + red[1][c] + red[2][c] + red[3][c]) / fcnt;
    float istd = rsqrtf(var + EPS);
    float wv = weight[c], b = bias[c];
    for (int n = lo + r; n < hi; n += 4) {
        size_t o = (size_t)n * 64 + c;
        out[o] = wv * (out[o] - am) * istd + b;
    }
}

// ---------------- launch ----------------
extern "C" void kernel_launch(void* const* d_in, const int* in_sizes, int n_in,
                              void* d_out, int out_size)
{
    (void)in_sizes; (void)n_in; (void)out_size;
    const float* h      = (const float*)d_in[0];
    const float* ea     = (const float*)d_in[1];
    const int*   eidx   = (const int*)d_in[2];
    const int*   batch  = (const int*)d_in[3];
    const float* msg_w1 = (const float*)d_in[4];
    const float* msg_b1 = (const float*)d_in[5];
    const float* msg_w2 = (const float*)d_in[6];
    const float* msg_b2 = (const float*)d_in[7];
    const float* upd_w1 = (const float*)d_in[8];
    const float* upd_b1 = (const float*)d_in[9];
    const float* upd_w2 = (const float*)d_in[10];
    const float* upd_b2 = (const float*)d_in[11];
    const float* gn_w   = (const float*)d_in[12];
    const float* gn_b   = (const float*)d_in[13];
    const float* gn_a   = (const float*)d_in[14];
    float* out = (float*)d_out;

    cudaFuncSetAttribute(p_kernel,    cudaFuncAttributeMaxDynamicSharedMemorySize, SMEM_P);
    cudaFuncSetAttribute(edge_kernel, cudaFuncAttributeMaxDynamicSharedMemorySize, SMEM_E);
    cudaFuncSetAttribute(node_kernel, cudaFuncAttributeMaxDynamicSharedMemorySize, SMEM_N);

    zero_agg_kernel<<<(NN * 64) / 256, 256>>>();
    prep_w1et<<<256, 32>>>(msg_w1);
    prep_w2t<<<64, 256>>>(msg_w2);
    prep_wPt<<<768, 64>>>(msg_w1, upd_w1, msg_b1, upd_b1);
    prep_uw1at<<<256, 64>>>(upd_w1);
    prep_uw2t<<<64, 256>>>(upd_w2);
    p_kernel<<<(NN + 127) / 128, 256, SMEM_P>>>(h);
    edge_kernel<<<148, 384, SMEM_E>>>(ea, eidx, msg_b2);
    node_kernel<<<148, 256, SMEM_N>>>(h, upd_b2, out);
    graphnorm_kernel<<<NG, 256>>>(batch, gn_w, gn_b, gn_a, out);
}

// round 15
// speedup vs baseline: 3.9004x; 1.2862x over previous
#include <cuda_runtime.h>
#include <cuda_fp16.h>
#include <cstdint>

#define NN 50000
#define NE 800000
#define NG 64
#define EPS 1e-5f

// ---------------- scratch ----------------
__device__ float g_P[(size_t)NN * 768];  // [0:256) msg dst-proj+b1 | [256:512) msg src-proj | [512:768) upd h-proj+ub1
__device__ float g_agg[(size_t)NN * 64];
__device__ float g_bP[768];
__device__ __align__(16) __half g_w1et_h[256 * 32];   // msg W1 edge rows ^T [n][k]
__device__ __align__(16) __half g_w2t_h[64 * 256];    // msg W2^T [c][j]
__device__ __align__(16) __half g_wPt_h[768 * 64];    // P weights^T [o][k]
__device__ __align__(16) __half g_uw1at_h[256 * 64];  // upd W1 agg rows ^T
__device__ __align__(16) __half g_uw2t_h[64 * 256];   // upd W2^T

__device__ __forceinline__ float silu(float t) { return t / (1.0f + __expf(-t)); }
__device__ __forceinline__ unsigned h2bits(float a, float b) {
    __half2 h = __floats2half2_rn(a, b);
    return *(unsigned*)&h;
}
// mma.sync m16n8k16 f16 inputs, f32 accum (baseline PTX -> fallback HMMA on sm_103)
__device__ __forceinline__ void mma_f16(float& d0, float& d1, float& d2, float& d3,
                                        unsigned a0, unsigned a1, unsigned a2, unsigned a3,
                                        unsigned b0, unsigned b1) {
    asm volatile("mma.sync.aligned.m16n8k16.row.col.f32.f16.f16.f32 "
                 "{%0,%1,%2,%3}, {%4,%5,%6,%7}, {%8,%9}, {%0,%1,%2,%3};"
                 : "+f"(d0), "+f"(d1), "+f"(d2), "+f"(d3)
                 : "r"(a0), "r"(a1), "r"(a2), "r"(a3), "r"(b0), "r"(b1));
}

// ---------------- prep ----------------
__global__ void zero_agg_kernel() {
    int i = blockIdx.x * blockDim.x + threadIdx.x;
    if (i < NN * 64) g_agg[i] = 0.0f;
}
__global__ void prep_all(const float* __restrict__ mw1, const float* __restrict__ uw1,
                         const float* __restrict__ mb1, const float* __restrict__ ub1,
                         const float* __restrict__ mw2, const float* __restrict__ uw2)
{   // <<<768, 256>>>
    int o = blockIdx.x, t = threadIdx.x;
    if (t < 64) {
        float v;
        if (o < 256)      v = mw1[(size_t)t * 256 + o];
        else if (o < 512) v = mw1[(size_t)(64 + t) * 256 + (o - 256)];
        else              v = uw1[(size_t)t * 256 + (o - 512)];
        g_wPt_h[o * 64 + t] = __float2half_rn(v);
        if (t == 0) g_bP[o] = (o < 256) ? mb1[o] : (o < 512 ? 0.0f : ub1[o - 512]);
    }
    if (o < 256) {
        if (t >= 64 && t < 96)   g_w1et_h[o * 32 + (t - 64)]  = __float2half_rn(mw1[(size_t)(128 + (t - 64)) * 256 + o]);
        if (t >= 96 && t < 160)  g_uw1at_h[o * 64 + (t - 96)] = __float2half_rn(uw1[(size_t)(64 + (t - 96)) * 256 + o]);
    }
    if (o < 64) {
        g_w2t_h[o * 256 + t]  = __float2half_rn(mw2[(size_t)t * 64 + o]);
        g_uw2t_h[o * 256 + t] = __float2half_rn(uw2[(size_t)t * 64 + o]);
    }
}

// ---------------- P kernel: g_P[n] = h[n] @ Wp + bP  (f16 MMA) ----------------
// smem: sH half[128][72] @0 (18432B), sW half[64][72] @18432 (9216B)
#define SMEM_P 27648
__global__ __launch_bounds__(256) void p_kernel(const float* __restrict__ h) {
    extern __shared__ __align__(16) char smraw[];
    __half* sH = (__half*)smraw;
    __half* sW = (__half*)(smraw + 18432);
    const unsigned* Hw = (const unsigned*)sH;
    const unsigned* Ww = (const unsigned*)sW;
    int tid = threadIdx.x, w = tid >> 5, lane = tid & 31;
    int r4 = lane >> 2, c4 = lane & 3, n0 = blockIdx.x * 128, R0 = 16 * w;

    for (int i = tid; i < 128 * 16; i += 256) {
        int r = i >> 4, j4 = (i & 15) * 4;
        int n = n0 + r; if (n >= NN) n = NN - 1;
        float4 v = *(const float4*)(h + (size_t)n * 64 + j4);
        uint2 u = {h2bits(v.x, v.y), h2bits(v.z, v.w)};
        *(uint2*)(sH + r * 72 + j4) = u;
    }
#pragma unroll 1
    for (int q = 0; q < 12; q++) {
        __syncthreads();
        for (int i = tid; i < 64 * 16; i += 256) {
            int r = i >> 4, j4 = (i & 15) * 4;
            *(uint2*)(sW + r * 72 + j4) = *(const uint2*)(g_wPt_h + (size_t)(q * 64 + r) * 64 + j4);
        }
        __syncthreads();
        int cb = 64 * q + 2 * c4;
        float acc[8][4];
#pragma unroll
        for (int t = 0; t < 8; t++) {
            float2 bb = *(const float2*)(g_bP + cb + 8 * t);
            acc[t][0] = bb.x; acc[t][1] = bb.y; acc[t][2] = bb.x; acc[t][3] = bb.y;
        }
#pragma unroll
        for (int ks = 0; ks < 4; ks++) {
            int ka = 8 * ks;
            unsigned a0 = Hw[(R0 + r4) * 36 + c4 + ka];
            unsigned a1 = Hw[(R0 + 8 + r4) * 36 + c4 + ka];
            unsigned a2 = Hw[(R0 + r4) * 36 + c4 + 4 + ka];
            unsigned a3 = Hw[(R0 + 8 + r4) * 36 + c4 + 4 + ka];
#pragma unroll
            for (int t = 0; t < 8; t++) {
                int nr = (8 * t + r4) * 36 + c4 + ka;
                mma_f16(acc[t][0], acc[t][1], acc[t][2], acc[t][3], a0, a1, a2, a3, Ww[nr], Ww[nr + 4]);
            }
        }
        int na = n0 + R0 + r4, nb = na + 8;
#pragma unroll
        for (int t = 0; t < 8; t++) {
            int col = cb + 8 * t;
            if (na < NN) *(float2*)(g_P + (size_t)na * 768 + col) = make_float2(acc[t][0], acc[t][1]);
            if (nb < NN) *(float2*)(g_P + (size_t)nb * 768 + col) = make_float2(acc[t][2], acc[t][3]);
        }
    }
}

// ---------------- edge kernel: persistent, warp-independent 16-edge tiles, f16 MMA ----------------
// smem bytes: W1E half[256][40]@0 (20480) | W2 half[64][264]@20480 (33792)
//             EA 14x half[16][40] @54272+w*1280 | T 14x half[16][264] @72192+w*8448
#define SMEM_E 190464
__global__ __launch_bounds__(448, 1) void edge_kernel(
    const float* __restrict__ ea, const int* __restrict__ eidx, const float* __restrict__ b2)
{
    extern __shared__ __align__(16) char smraw[];
    __half* sW1e = (__half*)smraw;
    __half* sW2  = (__half*)(smraw + 20480);
    int tid = threadIdx.x, w = tid >> 5, lane = tid & 31;
    int r4 = lane >> 2, c4 = lane & 3;
    __half* sEA = (__half*)(smraw + 54272 + w * 1280);
    __half* sT  = (__half*)(smraw + 72192 + w * 8448);
    const unsigned* W1w = (const unsigned*)sW1e;
    const unsigned* W2w = (const unsigned*)sW2;
    const unsigned* EAw = (const unsigned*)sEA;
    const unsigned* Tw  = (const unsigned*)sT;
    unsigned* Tst = (unsigned*)sT;

    for (int i = tid; i < 256 * 8; i += 448) {
        int r = i >> 3, j4 = (i & 7) * 4;
        *(uint2*)(sW1e + r * 40 + j4) = *(const uint2*)(g_w1et_h + r * 32 + j4);
    }
    for (int i = tid; i < 64 * 64; i += 448) {
        int c = i >> 6, j4 = (i & 63) * 4;
        *(uint2*)(sW2 + c * 264 + j4) = *(const uint2*)(g_w2t_h + c * 256 + j4);
    }
    float2 b2c[8];
#pragma unroll
    for (int t = 0; t < 8; t++) b2c[t] = *(const float2*)(b2 + 8 * t + 2 * c4);
    __syncthreads();

    const int nw = gridDim.x * 14;
#pragma unroll 1
    for (int tile = blockIdx.x * 14 + w; tile < NE / 16; tile += nw) {
        int e0 = tile * 16;
        int my = (lane < 16) ? eidx[NE + e0 + lane] : eidx[e0 + lane - 16];  // dst | src
        int d0 = __shfl_sync(0xffffffffu, my, r4);
        int d1 = __shfl_sync(0xffffffffu, my, 8 + r4);
        int s0 = __shfl_sync(0xffffffffu, my, 16 + r4);
        int s1 = __shfl_sync(0xffffffffu, my, 24 + r4);
        __syncwarp();
        {   // stage ea tile (16 x 32) -> f16
            int row = lane >> 1, cc = (lane & 1) * 16;
            const float4* srcp = (const float4*)(ea + (size_t)(e0 + row) * 32 + cc);
#pragma unroll
            for (int i = 0; i < 4; i++) {
                float4 v = srcp[i];
                uint2 u = {h2bits(v.x, v.y), h2bits(v.z, v.w)};
                *(uint2*)(sEA + row * 40 + cc + 4 * i) = u;
            }
        }
        __syncwarp();
        const float* Pd0 = g_P + (size_t)d0 * 768;
        const float* Pd1 = g_P + (size_t)d1 * 768;
        const float* Ps0 = g_P + (size_t)s0 * 768 + 256;
        const float* Ps1 = g_P + (size_t)s1 * 768 + 256;

        float acc2[8][4];
#pragma unroll
        for (int t = 0; t < 8; t++) { acc2[t][0]=acc2[t][1]=acc2[t][2]=acc2[t][3]=0.0f; }

#pragma unroll 1
        for (int q = 0; q < 4; q++) {
            int cb = 64 * q + 2 * c4;
            float acc1[8][4];
#pragma unroll
            for (int t = 0; t < 8; t++) {   // init: P_dst(+b1) + P_src
                float2 pa = *(const float2*)(Pd0 + cb + 8 * t);
                float2 pb = *(const float2*)(Ps0 + cb + 8 * t);
                float2 pc = *(const float2*)(Pd1 + cb + 8 * t);
                float2 pd = *(const float2*)(Ps1 + cb + 8 * t);
                acc1[t][0] = pa.x + pb.x; acc1[t][1] = pa.y + pb.y;
                acc1[t][2] = pc.x + pd.x; acc1[t][3] = pc.y + pd.y;
            }
#pragma unroll
            for (int ks = 0; ks < 2; ks++) {   // + ea @ W1e (k=32 -> 2 k16 steps)
                int ka = 8 * ks;
                unsigned a0 = EAw[r4 * 20 + c4 + ka];
                unsigned a1 = EAw[(8 + r4) * 20 + c4 + ka];
                unsigned a2 = EAw[r4 * 20 + c4 + 4 + ka];
                unsigned a3 = EAw[(8 + r4) * 20 + c4 + 4 + ka];
#pragma unroll
                for (int t = 0; t < 8; t++) {
                    int nr = (64 * q + 8 * t + r4) * 20 + c4 + ka;
                    mma_f16(acc1[t][0], acc1[t][1], acc1[t][2], acc1[t][3], a0, a1, a2, a3, W1w[nr], W1w[nr + 4]);
                }
            }
            // silu -> warp-private sT, CHUNK-LOCAL u32 cols 0..31 (read side matches below)
#pragma unroll
            for (int t = 0; t < 8; t++) {
                Tst[r4 * 132 + 4 * t + c4]       = h2bits(silu(acc1[t][0]), silu(acc1[t][1]));
                Tst[(8 + r4) * 132 + 4 * t + c4] = h2bits(silu(acc1[t][2]), silu(acc1[t][3]));
            }
            __syncwarp();
#pragma unroll
            for (int kc = 0; kc < 4; kc++) {   // acc2 += T_chunk @ W2_chunk (k=64 -> 4 k16 steps)
                int kta = 8 * kc;              // chunk-local T offset
                int kwb = 32 * q + 8 * kc;     // global W2 k offset
                unsigned a0 = Tw[r4 * 132 + kta + c4];
                unsigned a1 = Tw[(8 + r4) * 132 + kta + c4];
                unsigned a2 = Tw[r4 * 132 + kta + c4 + 4];
                unsigned a3 = Tw[(8 + r4) * 132 + kta + c4 + 4];
#pragma unroll
                for (int t = 0; t < 8; t++) {
                    int nr = (8 * t + r4) * 132 + kwb + c4;
                    mma_f16(acc2[t][0], acc2[t][1], acc2[t][2], acc2[t][3], a0, a1, a2, a3, W2w[nr], W2w[nr + 4]);
                }
            }
            __syncwarp();
        }
        float* A0 = g_agg + (size_t)d0 * 64;
        float* A1 = g_agg + (size_t)d1 * 64;
#pragma unroll
        for (int t = 0; t < 8; t++) {
            int col = 8 * t + 2 * c4;
            float x0 = acc2[t][0] + b2c[t].x, x1 = acc2[t][1] + b2c[t].y;
            float x2 = acc2[t][2] + b2c[t].x, x3 = acc2[t][3] + b2c[t].y;
            asm volatile("red.global.add.v2.f32 [%0], {%1,%2};" :: "l"(A0 + col), "f"(x0), "f"(x1) : "memory");
            asm volatile("red.global.add.v2.f32 [%0], {%1,%2};" :: "l"(A1 + col), "f"(x2), "f"(x3) : "memory");
        }
    }
}

// ---------------- node kernel: persistent, warp-independent 16-node tiles, f16 MMA ----------------
// smem bytes: UW1A half[256][72]@0 (36864) | UW2 half[64][264]@36864 (33792)
//             AG 12x half[16][72] @70656+w*2304 | T 12x half[16][264] @98304+w*8448
#define SMEM_N 199680
__global__ __launch_bounds__(384, 1) void node_kernel(
    const float* __restrict__ h, const float* __restrict__ ub2, float* __restrict__ out)
{
    extern __shared__ __align__(16) char smraw[];
    __half* sUW1 = (__half*)smraw;
    __half* sUW2 = (__half*)(smraw + 36864);
    int tid = threadIdx.x, w = tid >> 5, lane = tid & 31;
    int r4 = lane >> 2, c4 = lane & 3;
    __half* sAG = (__half*)(smraw + 70656 + w * 2304);
    __half* sT  = (__half*)(smraw + 98304 + w * 8448);
    const unsigned* W1w = (const unsigned*)sUW1;
    const unsigned* W2w = (const unsigned*)sUW2;
    const unsigned* AGw = (const unsigned*)sAG;
    const unsigned* Tw  = (const unsigned*)sT;
    unsigned* Tst = (unsigned*)sT;

    for (int i = tid; i < 256 * 16; i += 384) {
        int r = i >> 4, j4 = (i & 15) * 4;
        *(uint2*)(sUW1 + r * 72 + j4) = *(const uint2*)(g_uw1at_h + r * 64 + j4);
    }
    for (int i = tid; i < 64 * 64; i += 384) {
        int c = i >> 6, j4 = (i & 63) * 4;
        *(uint2*)(sUW2 + c * 264 + j4) = *(const uint2*)(g_uw2t_h + c * 256 + j4);
    }
    float2 bc[8];
#pragma unroll
    for (int t = 0; t < 8; t++) bc[t] = *(const float2*)(ub2 + 8 * t + 2 * c4);
    __syncthreads();

    const int nw = gridDim.x * 12;
#pragma unroll 1
    for (int tile = blockIdx.x * 12 + w; tile < NN / 16; tile += nw) {
        int n0 = tile * 16;
        {   // stage agg tile (16 x 64) -> f16
            int row = lane >> 1, cc = (lane & 1) * 32;
            const float4* srcp = (const float4*)(g_agg + (size_t)(n0 + row) * 64 + cc);
#pragma unroll
            for (int i = 0; i < 8; i++) {
                float4 v = srcp[i];
                uint2 u = {h2bits(v.x, v.y), h2bits(v.z, v.w)};
                *(uint2*)(sAG + row * 72 + cc + 4 * i) = u;
            }
        }
        __syncwarp();
        const float* Pu0 = g_P + (size_t)(n0 + r4) * 768 + 512;
        const float* Pu1 = g_P + (size_t)(n0 + 8 + r4) * 768 + 512;

        float acc2[8][4];
#pragma unroll
        for (int t = 0; t < 8; t++) { acc2[t][0]=acc2[t][1]=acc2[t][2]=acc2[t][3]=0.0f; }

#pragma unroll 1
        for (int q = 0; q < 4; q++) {
            int cb = 64 * q + 2 * c4;
            float acc1[8][4];
#pragma unroll
            for (int t = 0; t < 8; t++) {   // init: h-proj (+ub1)
                float2 pa = *(const float2*)(Pu0 + cb + 8 * t);
                float2 pc = *(const float2*)(Pu1 + cb + 8 * t);
                acc1[t][0] = pa.x; acc1[t][1] = pa.y; acc1[t][2] = pc.x; acc1[t][3] = pc.y;
            }
#pragma unroll
            for (int ks = 0; ks < 4; ks++) {   // + agg @ Uw1a (k=64 -> 4 k16 steps)
                int ka = 8 * ks;
                unsigned a0 = AGw[r4 * 36 + c4 + ka];
                unsigned a1 = AGw[(8 + r4) * 36 + c4 + ka];
                unsigned a2 = AGw[r4 * 36 + c4 + 4 + ka];
                unsigned a3 = AGw[(8 + r4) * 36 + c4 + 4 + ka];
#pragma unroll
                for (int t = 0; t < 8; t++) {
                    int nr = (64 * q + 8 * t + r4) * 36 + c4 + ka;
                    mma_f16(acc1[t][0], acc1[t][1], acc1[t][2], acc1[t][3], a0, a1, a2, a3, W1w[nr], W1w[nr + 4]);
                }
            }
            // silu -> warp-private sT, CHUNK-LOCAL
#pragma unroll
            for (int t = 0; t < 8; t++) {
                Tst[r4 * 132 + 4 * t + c4]       = h2bits(silu(acc1[t][0]), silu(acc1[t][1]));
                Tst[(8 + r4) * 132 + 4 * t + c4] = h2bits(silu(acc1[t][2]), silu(acc1[t][3]));
            }
            __syncwarp();
#pragma unroll
            for (int kc = 0; kc < 4; kc++) {
                int kta = 8 * kc;              // chunk-local T offset
                int kwb = 32 * q + 8 * kc;     // global W2 k offset
                unsigned a0 = Tw[r4 * 132 + kta + c4];
                unsigned a1 = Tw[(8 + r4) * 132 + kta + c4];
                unsigned a2 = Tw[r4 * 132 + kta + c4 + 4];
                unsigned a3 = Tw[(8 + r4) * 132 + kta + c4 + 4];
#pragma unroll
                for (int t = 0; t < 8; t++) {
                    int nr = (8 * t + r4) * 132 + kwb + c4;
                    mma_f16(acc2[t][0], acc2[t][1], acc2[t][2], acc2[t][3], a0, a1, a2, a3, W2w[nr], W2w[nr + 4]);
                }
            }
            __syncwarp();
        }
        int na = n0 + r4, nb = n0 + 8 + r4;
#pragma unroll
        for (int t = 0; t < 8; t++) {   // residual + bias
            int col = 8 * t + 2 * c4;
            float2 h0 = *(const float2*)(h + (size_t)na * 64 + col);
            float2 h1 = *(const float2*)(h + (size_t)nb * 64 + col);
            *(float2*)(out + (size_t)na * 64 + col) =
                make_float2(h0.x + acc2[t][0] + bc[t].x, h0.y + acc2[t][1] + bc[t].y);
            *(float2*)(out + (size_t)nb * 64 + col) =
                make_float2(h1.x + acc2[t][2] + bc[t].x, h1.y + acc2[t][3] + bc[t].y);
        }
    }
}

// ---------------- GraphNorm (4-way channel split) ----------------
__device__ __forceinline__ int lbound32(const int* a, int n, int key) {
    int lo = 0, hi = n;
    while (lo < hi) { int mid = (lo + hi) >> 1; if (a[mid] < key) lo = mid + 1; else hi = mid; }
    return lo;
}
__global__ __launch_bounds__(256) void graphnorm_kernel(
    const int* __restrict__ batch, const float* __restrict__ weight,
    const float* __restrict__ bias, const float* __restrict__ alpha, float* __restrict__ out)
{
    int gph = blockIdx.x >> 2, cg = blockIdx.x & 3;
    __shared__ int s_lo, s_hi;
    __shared__ float red[16][17];
    if (threadIdx.x == 0) s_lo = lbound32(batch, NN, gph);
    if (threadIdx.x == 1) s_hi = lbound32(batch, NN, gph + 1);
    __syncthreads();
    int lo = s_lo, hi = s_hi;
    float fcnt = (float)max(hi - lo, 1);
    int ci = threadIdx.x & 15, r = threadIdx.x >> 4;
    int c = cg * 16 + ci;

    float sum = 0.0f;
    for (int n = lo + r; n < hi; n += 16) sum += out[(size_t)n * 64 + c];
    red[r][ci] = sum;
    __syncthreads();
    float mean = 0.0f;
#pragma unroll
    for (int i = 0; i < 16; i++) mean += red[i][ci];
    mean /= fcnt;
    float am = alpha[c] * mean;
    __syncthreads();

    float sq = 0.0f;
    for (int n = lo + r; n < hi; n += 16) { float d = out[(size_t)n * 64 + c] - am; sq += d * d; }
    red[r][ci] = sq;
    __syncthreads();
    float var = 0.0f;
#pragma unroll
    for (int i = 0; i < 16; i++) var += red[i][ci];
    var /= fcnt;
    float istd = rsqrtf(var + EPS);
    float wv = weight[c], b = bias[c];
    for (int n = lo + r; n < hi; n += 16) {
        size_t o = (size_t)n * 64 + c;
        out[o] = wv * (out[o] - am) * istd + b;
    }
}

// ---------------- launch ----------------
extern "C" void kernel_launch(void* const* d_in, const int* in_sizes, int n_in,
                              void* d_out, int out_size)
{
    (void)in_sizes; (void)n_in; (void)out_size;
    const float* h      = (const float*)d_in[0];
    const float* ea     = (const float*)d_in[1];
    const int*   eidx   = (const int*)d_in[2];
    const int*   batch  = (const int*)d_in[3];
    const float* msg_w1 = (const float*)d_in[4];
    const float* msg_b1 = (const float*)d_in[5];
    const float* msg_w2 = (const float*)d_in[6];
    const float* msg_b2 = (const float*)d_in[7];
    const float* upd_w1 = (const float*)d_in[8];
    const float* upd_b1 = (const float*)d_in[9];
    const float* upd_w2 = (const float*)d_in[10];
    const float* upd_b2 = (const float*)d_in[11];
    const float* gn_w   = (const float*)d_in[12];
    const float* gn_b   = (const float*)d_in[13];
    const float* gn_a   = (const float*)d_in[14];
    float* out = (float*)d_out;

    cudaFuncSetAttribute(p_kernel,    cudaFuncAttributeMaxDynamicSharedMemorySize, SMEM_P);
    cudaFuncSetAttribute(edge_kernel, cudaFuncAttributeMaxDynamicSharedMemorySize, SMEM_E);
    cudaFuncSetAttribute(node_kernel, cudaFuncAttributeMaxDynamicSharedMemorySize, SMEM_N);

    zero_agg_kernel<<<(NN * 64) / 256, 256>>>();
    prep_all<<<768, 256>>>(msg_w1, upd_w1, msg_b1, upd_b1, msg_w2, upd_w2);
    p_kernel<<<(NN + 127) / 128, 256, SMEM_P>>>(h);
    edge_kernel<<<148, 448, SMEM_E>>>(ea, eidx, msg_b2);
    node_kernel<<<148, 384, SMEM_N>>>(h, upd_b2, out);
    graphnorm_kernel<<<NG * 4, 256>>>(batch, gn_w, gn_b, gn_a, out);
}